// round 15
// baseline (speedup 1.0000x reference)
#include <cuda_runtime.h>
#include <cstdint>
#include <climits>

#define Bc 4
#define Fc 60082
#define Cc 14695
#define Dc 256
#define KNc 64
#define KHc 128
#define NTH 8                     // his slots per his block
#define MROWS 64                  // field rows per dense block (2 passes of 32)
#define NPREPB 34                 // 33 prep-task blocks + 1 bitmap block
#define NHIS ((Bc*KHc)/NTH)       // 64 his blocks
#define NCORR ((KNc + KHc) / 8 * Bc)        // 96 corr blocks
#define NMAIN ((Fc + MROWS - 1) / MROWS)    // 939 dense blocks
#define GRIDTOT (NPREPB + NHIS + NCORR + NMAIN)   // 1133
#define BMWORDS 1888              // ceil(60082/32)=1878, padded
#define SMEM_BYTES 8960

// Scratch (no allocation allowed) — __device__ globals.
__device__ __align__(16) float g_u[Dc];   // W_proj @ w_ff
__device__ float g_comp[Bc];              // company_mem . w_fc + b_fc
__device__ float g_c0;                    // b_proj . w_ff
__device__ float g_hisdot[Bc*KHc];        // leaky(rfe@W1+b1).w2v + c2 per his slot
__device__ unsigned g_bitmap[Bc*BMWORDS]; // touched-(b,f) bits; idempotent, never cleared
__device__ int   g_prep_done;             // 34 when prep+bitmap finished
__device__ int   g_his_done;              // 64 when his finished
__device__ int   g_all;                   // GRIDTOT when everything finished (last resets)

__device__ __forceinline__ float warp_sum(float v) {
    v += __shfl_xor_sync(0xffffffffu, v, 16);
    v += __shfl_xor_sync(0xffffffffu, v, 8);
    v += __shfl_xor_sync(0xffffffffu, v, 4);
    v += __shfl_xor_sync(0xffffffffu, v, 2);
    v += __shfl_xor_sync(0xffffffffu, v, 1);
    return v;
}

__device__ __forceinline__ float dot8(const float* __restrict__ a, const float* __restrict__ b) {
    float4 a0 = ((const float4*)a)[0], a1 = ((const float4*)a)[1];
    float4 b0 = ((const float4*)b)[0], b1 = ((const float4*)b)[1];
    return a0.x*b0.x + a0.y*b0.y + a0.z*b0.z + a0.w*b0.w
         + a1.x*b1.x + a1.y*b1.y + a1.z*b1.z + a1.w*b1.w;
}

__device__ __forceinline__ void spin_until(int* ctr, int target, unsigned ns) {
    volatile int* p = ctr;
    while (*p < target) { __nanosleep(ns); }
}

// ===========================================================================
// ONE kernel (round-14 structure = measured best, 18.9us). Block layout:
//   [0, 33)         prep    : g_u, g_comp, g_c0
//   33              bitmap  : touched-(b,f) bits from index lists only
//   [34, 98)        his     : g_hisdot (local w2v/c2)      -> g_his_done
//   [98, 194)       corr    : computes + stores touched rows directly
//   [194, 194+939)  dense   : streams field_table, bitmap-masked stores.
//                             NEW: pass-0 loads ISSUED BEFORE the prep gate —
//                             first 32KB/block streams while prep runs.
// Every block increments g_all at exit; the last one resets all counters
// for the next graph replay (no block ever waits on g_all -> deadlock-free).
// ===========================================================================
__global__ void __launch_bounds__(256) mega_kernel(
                            const float* __restrict__ field_table,
                            const float* __restrict__ field_emb,
                            const float* __restrict__ raw_field_embed,
                            const float* __restrict__ alpha_fields,
                            const float* __restrict__ w_ff,
                            const float* __restrict__ b_ff,
                            const float* __restrict__ W1,
                            const float* __restrict__ b1,
                            const float* __restrict__ W2,
                            const float* __restrict__ b2,
                            const float* __restrict__ W_proj,
                            const float* __restrict__ b_proj,
                            const float* __restrict__ theta,
                            const float* __restrict__ w_fc,
                            const float* __restrict__ b_fc,
                            const float* __restrict__ company_emb,
                            const float* __restrict__ comp_table,
                            const int*   __restrict__ com_id,
                            const int*   __restrict__ now_nodes,
                            const int*   __restrict__ his_nodes,
                            float* __restrict__ out)
{
    __shared__ __align__(16) unsigned char smraw[SMEM_BYTES];
    int t = threadIdx.x;
    int warp = t >> 5, lane = t & 31;
    int bid = blockIdx.x;

    if (bid < NPREPB - 1) {
        // ======================= prep =======================
        int wt = bid * 8 + warp;   // 0..263
        if (wt < Dc) {
            float s = warp_sum(dot8(W_proj + (size_t)wt*Dc + lane*8, w_ff + lane*8));
            if (lane == 0) g_u[wt] = s;
        } else if (wt < Dc + Bc) {
            int b   = wt - Dc;
            int cid = com_id[b];
            float th = theta[cid];
            float s = 0.f;
            #pragma unroll
            for (int i = 0; i < 8; i++) {
                int d = lane*8 + i;
                float m = (1.f - th) * company_emb[b*Dc + d] + th * comp_table[(size_t)cid*Dc + d];
                s += m * w_fc[d];
            }
            s = warp_sum(s);
            if (lane == 0) g_comp[b] = s + b_fc[0];
        } else if (wt == Dc + Bc) {
            float s = warp_sum(dot8(b_proj + lane*8, w_ff + lane*8));
            if (lane == 0) g_c0 = s;
        }
        __syncthreads();
        if (t == 0) { __threadfence(); atomicAdd(&g_prep_done, 1); }

    } else if (bid == NPREPB - 1) {
        // ======================= bitmap =======================
        // Touched bits from index lists only. Idempotent; never cleared.
        for (int e = t; e < Bc * (KNc + KHc); e += 256) {
            int b = e / (KNc + KHc);
            int i = e % (KNc + KHc);
            int f = (i < KNc) ? now_nodes[b*KNc + i] : his_nodes[b*KHc + (i - KNc)];
            atomicOr(&g_bitmap[b*BMWORDS + (f >> 5)], 1u << (f & 31));
        }
        __syncthreads();
        if (t == 0) { __threadfence(); atomicAdd(&g_prep_done, 1); }

    } else if (bid < NPREPB + NHIS) {
        // ======================= his =======================
        float (*rfe)[Dc] = (float (*)[Dc])smraw;                   // 8192 B
        float (*red)[4]  = (float (*)[4])(smraw + 8192);           // 128 B
        float* w2v_s     = (float*)(smraw + 8320);                 // 512 B
        float* c2_s      = (float*)(smraw + 8832);                 // 4 B
        int j = t & 127, h = t >> 7;
        int slot0 = (bid - NPREPB) * NTH;

        #pragma unroll
        for (int i = t; i < NTH*Dc/4; i += 256) {
            int n  = i >> 6;
            int c4 = i & 63;
            int f  = his_nodes[slot0 + n];
            ((float4*)rfe[n])[c4] = ((const float4*)(raw_field_embed + (size_t)f*Dc))[c4];
        }
        #pragma unroll
        for (int r = 0; r < 16; r++) {
            int jr = warp * 16 + r;
            float s = warp_sum(dot8(W2 + (size_t)jr*Dc + lane*8, w_ff + lane*8));
            if (lane == 0) w2v_s[jr] = s;
        }
        if (warp == 0) {
            float s = warp_sum(dot8(b2 + lane*8, w_ff + lane*8));
            if (lane == 0) *c2_s = s;
        }
        __syncthreads();

        float bj = b1[j];
        float acc0 = bj, acc1 = bj, acc2 = bj, acc3 = bj;
        int nb = h * 4;
        #pragma unroll 4
        for (int k = 0; k < Dc; k += 4) {
            float wa = W1[(size_t)(k+0)*(Dc/2) + j];
            float wb = W1[(size_t)(k+1)*(Dc/2) + j];
            float wc = W1[(size_t)(k+2)*(Dc/2) + j];
            float wd = W1[(size_t)(k+3)*(Dc/2) + j];
            float4 r0 = *(const float4*)&rfe[nb+0][k];
            float4 r1 = *(const float4*)&rfe[nb+1][k];
            float4 r2 = *(const float4*)&rfe[nb+2][k];
            float4 r3 = *(const float4*)&rfe[nb+3][k];
            acc0 += r0.x*wa + r0.y*wb + r0.z*wc + r0.w*wd;
            acc1 += r1.x*wa + r1.y*wb + r1.z*wc + r1.w*wd;
            acc2 += r2.x*wa + r2.y*wb + r2.z*wc + r2.w*wd;
            acc3 += r3.x*wa + r3.y*wb + r3.z*wc + r3.w*wd;
        }

        float wv = w2v_s[j];
        float p0 = ((acc0 >= 0.f) ? acc0 : 0.01f*acc0) * wv;
        float p1 = ((acc1 >= 0.f) ? acc1 : 0.01f*acc1) * wv;
        float p2 = ((acc2 >= 0.f) ? acc2 : 0.01f*acc2) * wv;
        float p3 = ((acc3 >= 0.f) ? acc3 : 0.01f*acc3) * wv;

        p0 = warp_sum(p0); p1 = warp_sum(p1); p2 = warp_sum(p2); p3 = warp_sum(p3);
        if (lane == 0) { red[warp][0]=p0; red[warp][1]=p1; red[warp][2]=p2; red[warp][3]=p3; }
        __syncthreads();
        if (t < NTH) {
            int n = t, hh = n >> 2, nn = n & 3;
            float s = red[hh*4+0][nn] + red[hh*4+1][nn] + red[hh*4+2][nn] + red[hh*4+3][nn];
            g_hisdot[slot0 + n] = s + *c2_s;
        }
        __syncthreads();
        if (t == 0) { __threadfence(); atomicAdd(&g_his_done, 1); }

    } else if (bid < NPREPB + NHIS + NCORR) {
        // ======================= corr =======================
        float* u_s   = (float*)smraw;             // 1024 B
        float* wff_s = (float*)(smraw + 1024);    // 1024 B
        int*   now_s = (int*)(smraw + 2048);      // 256 B
        int*   his_s = (int*)(smraw + 2304);      // 512 B
        int cid = bid - NPREPB - NHIS;     // 0..95
        int b   = cid / ((KNc + KHc)/8);   // 0..3
        int xb  = cid % ((KNc + KHc)/8);   // 0..23

        // index lists + w_ff don't depend on prep — stage them BEFORE the gate
        wff_s[t] = w_ff[t];
        if (t < KNc) now_s[t] = now_nodes[b*KNc + t];
        if (t < KHc) his_s[t] = his_nodes[b*KHc + t];

        if (t == 0) spin_until(&g_prep_done, NPREPB, 128);
        __syncthreads();
        __threadfence();
        u_s[t] = g_u[t];
        __syncthreads();

        float cb = g_comp[b] + b_ff[0];
        float c0 = g_c0;

        int node = xb * 8 + warp;          // 0 .. 191
        int f = (node < KNc) ? now_s[node] : his_s[node - KNc];

        float a1 = dot8(field_table + (size_t)f*Dc + lane*8, u_s   + lane*8);
        float a2 = dot8(field_emb   + (size_t)f*Dc + lane*8, wff_s + lane*8);
        a1 = warp_sum(a1);
        a2 = warp_sum(a2);

        bool inNow = (now_s[lane] == f) || (now_s[lane + 32] == f);
        unsigned mN = __ballot_sync(0xffffffffu, inNow);

        int jmin = INT_MAX;
        #pragma unroll
        for (int r = 0; r < 4; r++) {
            int j = lane + r*32;
            if (his_s[j] == f && j < jmin) jmin = j;
        }
        #pragma unroll
        for (int o = 16; o > 0; o >>= 1) {
            int oth = __shfl_xor_sync(0xffffffffu, jmin, o);
            jmin = min(jmin, oth);
        }

        float alpha = alpha_fields[f];
        float val = (1.f - alpha) * (a1 + c0) + cb;
        if (mN) val += alpha * a2;

        if (lane == 0) {
            if (jmin != INT_MAX) {
                spin_until(&g_his_done, NHIS, 128);
                __threadfence();
                val += alpha * g_hisdot[b*KHc + jmin];
            }
            // store immediately — dense skips touched entries via bitmap.
            out[(size_t)b*Fc + f] = val;
        }

    } else {
        // ======================= dense =======================
        float4* u_s4 = (float4*)smraw;   // 1 KB
        int db = bid - NPREPB - NHIS - NCORR;   // 0..NMAIN-1

        int grp = lane >> 3, sub = lane & 7;
        int blockBase = db * MROWS;

        // ---- PASS-0 LOADS ISSUED BEFORE THE PREP GATE (input-only data) ----
        int r0a = blockBase + warp * 4;
        int fa  = r0a + grp;
        int fca = (fa < Fc) ? fa : (Fc - 1);
        const float4* rowA = (const float4*)(field_table + (size_t)fca * Dc);
        float4 v[8];
        #pragma unroll
        for (int i = 0; i < 8; i++) v[i] = rowA[sub + 8*i];

        // ---- gate on prep (loads already in flight) ----
        if (t == 0) spin_until(&g_prep_done, NPREPB, 128);
        __syncthreads();
        __threadfence();

        if (t < Dc/4) u_s4[t] = ((const float4*)g_u)[t];
        __syncthreads();

        float addb = g_comp[lane & 3] + b_ff[0] + g_c0;

        #pragma unroll
        for (int p = 0; p < 2; p++) {
            int r0 = blockBase + p * 32 + warp * 4;
            if (p == 1) {
                int f  = r0 + grp;
                int fc = (f < Fc) ? f : (Fc - 1);
                const float4* row = (const float4*)(field_table + (size_t)fc * Dc);
                #pragma unroll
                for (int i = 0; i < 8; i++) v[i] = row[sub + 8*i];
            }

            float acc = 0.f;
            #pragma unroll
            for (int i = 0; i < 8; i++) {
                float4 uu = u_s4[sub + 8*i];
                acc += v[i].x*uu.x + v[i].y*uu.y + v[i].z*uu.z + v[i].w*uu.w;
            }
            // reduce within 8-lane group
            acc += __shfl_xor_sync(0xffffffffu, acc, 4);
            acc += __shfl_xor_sync(0xffffffffu, acc, 2);
            acc += __shfl_xor_sync(0xffffffffu, acc, 1);
            // assemble the 4 group sums warp-wide
            float t1 = __shfl_xor_sync(0xffffffffu, acc, 8);
            float t2 = __shfl_xor_sync(0xffffffffu, acc, 16);
            float t3 = __shfl_xor_sync(0xffffffffu, t1, 16);

            if (lane < 8) {
                int b = lane & 3, h = lane >> 2;
                int fr = r0 + 2*h;
                if (fr < Fc) {          // Fc even & fr even -> pair fully in/out
                    unsigned w  = g_bitmap[b*BMWORDS + (fr >> 5)];
                    unsigned m0 = (w >> (fr & 31)) & 1u;
                    unsigned m1 = (w >> ((fr & 31) + 1)) & 1u;
                    float2 q;
                    q.x = (h ? t2 : acc) + addb;
                    q.y = (h ? t3 : t1)  + addb;
                    if (!(m0 | m1)) {
                        *(float2*)(out + (size_t)b*Fc + fr) = q;
                    } else {
                        if (!m0) out[(size_t)b*Fc + fr]     = q.x;
                        if (!m1) out[(size_t)b*Fc + fr + 1] = q.y;
                    }
                }
            }
        }
    }

    // ---- common exit: last block out resets counters for the next replay ----
    __syncthreads();
    if (t == 0) {
        __threadfence();
        int v = atomicAdd(&g_all, 1);
        if (v == GRIDTOT - 1) {      // no block ever waits on g_all -> safe
            g_prep_done = 0;
            g_his_done  = 0;
            g_all       = 0;
        }
    }
}

// ---------------------------------------------------------------------------
extern "C" void kernel_launch(void* const* d_in, const int* in_sizes, int n_in,
                              void* d_out, int out_size)
{
    const float* company_emb     = (const float*)d_in[0];
    const float* field_emb       = (const float*)d_in[1];
    const float* raw_field_embed = (const float*)d_in[2];
    const float* comp_table      = (const float*)d_in[3];
    const float* field_table     = (const float*)d_in[4];
    const float* W_proj          = (const float*)d_in[5];
    const float* b_proj          = (const float*)d_in[6];
    const float* theta           = (const float*)d_in[7];
    const float* alpha_fields    = (const float*)d_in[8];
    const float* w_ff            = (const float*)d_in[9];
    const float* b_ff            = (const float*)d_in[10];
    const float* w_fc            = (const float*)d_in[11];
    const float* b_fc            = (const float*)d_in[12];
    const float* W1              = (const float*)d_in[13];
    const float* b1              = (const float*)d_in[14];
    const float* W2              = (const float*)d_in[15];
    const float* b2              = (const float*)d_in[16];
    const int*   now_nodes       = (const int*)d_in[17];
    const int*   his_nodes       = (const int*)d_in[18];
    const int*   com_id          = (const int*)d_in[19];
    float* out = (float*)d_out;

    mega_kernel<<<GRIDTOT, 256>>>(
        field_table, field_emb, raw_field_embed, alpha_fields, w_ff, b_ff,
        W1, b1, W2, b2, W_proj, b_proj, theta, w_fc, b_fc,
        company_emb, comp_table, com_id, now_nodes, his_nodes, out);
}

// round 16
// speedup vs baseline: 1.0824x; 1.0824x over previous
#include <cuda_runtime.h>
#include <cstdint>
#include <climits>

#define Bc 4
#define Fc 60082
#define Cc 14695
#define Dc 256
#define KNc 64
#define KHc 128
#define NTH 8                     // his slots per his block
#define MROWS 160                 // field rows per dense block (5 passes of 32)
#define NPREPB 34                 // 33 prep-task blocks + 1 bitmap block
#define NHIS ((Bc*KHc)/NTH)       // 64 his blocks
#define NCORR ((KNc + KHc) / 8 * Bc)        // 96 corr blocks
#define NMAIN ((Fc + MROWS - 1) / MROWS)    // 376 dense blocks
#define GRIDTOT (NPREPB + NHIS + NCORR + NMAIN)   // 570 -> SINGLE WAVE (4 blk/SM * 148 = 592)
#define BMWORDS 1888              // ceil(60082/32)=1878, padded
#define SMEM_BYTES 8960

// Scratch (no allocation allowed) — __device__ globals.
__device__ __align__(16) float g_u[Dc];   // W_proj @ w_ff
__device__ float g_comp[Bc];              // company_mem . w_fc + b_fc
__device__ float g_c0;                    // b_proj . w_ff
__device__ float g_hisdot[Bc*KHc];        // leaky(rfe@W1+b1).w2v + c2 per his slot
__device__ unsigned g_bitmap[Bc*BMWORDS]; // touched-(b,f) bits; idempotent, never cleared
__device__ int   g_prep_done;             // 34 when prep+bitmap finished
__device__ int   g_his_done;              // 64 when his finished
__device__ int   g_all;                   // GRIDTOT when everything finished (last resets)

__device__ __forceinline__ float warp_sum(float v) {
    v += __shfl_xor_sync(0xffffffffu, v, 16);
    v += __shfl_xor_sync(0xffffffffu, v, 8);
    v += __shfl_xor_sync(0xffffffffu, v, 4);
    v += __shfl_xor_sync(0xffffffffu, v, 2);
    v += __shfl_xor_sync(0xffffffffu, v, 1);
    return v;
}

__device__ __forceinline__ float dot8(const float* __restrict__ a, const float* __restrict__ b) {
    float4 a0 = ((const float4*)a)[0], a1 = ((const float4*)a)[1];
    float4 b0 = ((const float4*)b)[0], b1 = ((const float4*)b)[1];
    return a0.x*b0.x + a0.y*b0.y + a0.z*b0.z + a0.w*b0.w
         + a1.x*b1.x + a1.y*b1.y + a1.z*b1.z + a1.w*b1.w;
}

__device__ __forceinline__ void spin_until(int* ctr, int target, unsigned ns) {
    volatile int* p = ctr;
    while (*p < target) { __nanosleep(ns); }
}

// ===========================================================================
// ONE kernel, SINGLE WAVE (570 blocks <= 592 resident slots @4 blk/SM).
//   [0, 33)        prep    : g_u, g_comp, g_c0
//   33             bitmap  : touched-(b,f) bits from index lists only
//   [34, 98)       his     : g_hisdot (local w2v/c2)      -> g_his_done
//   [98, 194)      corr    : computes + stores touched rows directly
//   [194, 194+376) dense   : 160 rows each (5 passes of 32); pass-0 loads
//                            issued BEFORE the prep gate; bitmap-masked stores
// Every block increments g_all at exit; the last one resets all counters
// for the next graph replay (no block ever waits on g_all -> deadlock-free).
// ===========================================================================
__global__ void __launch_bounds__(256, 4) mega_kernel(
                            const float* __restrict__ field_table,
                            const float* __restrict__ field_emb,
                            const float* __restrict__ raw_field_embed,
                            const float* __restrict__ alpha_fields,
                            const float* __restrict__ w_ff,
                            const float* __restrict__ b_ff,
                            const float* __restrict__ W1,
                            const float* __restrict__ b1,
                            const float* __restrict__ W2,
                            const float* __restrict__ b2,
                            const float* __restrict__ W_proj,
                            const float* __restrict__ b_proj,
                            const float* __restrict__ theta,
                            const float* __restrict__ w_fc,
                            const float* __restrict__ b_fc,
                            const float* __restrict__ company_emb,
                            const float* __restrict__ comp_table,
                            const int*   __restrict__ com_id,
                            const int*   __restrict__ now_nodes,
                            const int*   __restrict__ his_nodes,
                            float* __restrict__ out)
{
    __shared__ __align__(16) unsigned char smraw[SMEM_BYTES];
    int t = threadIdx.x;
    int warp = t >> 5, lane = t & 31;
    int bid = blockIdx.x;

    if (bid < NPREPB - 1) {
        // ======================= prep =======================
        int wt = bid * 8 + warp;   // 0..263
        if (wt < Dc) {
            float s = warp_sum(dot8(W_proj + (size_t)wt*Dc + lane*8, w_ff + lane*8));
            if (lane == 0) g_u[wt] = s;
        } else if (wt < Dc + Bc) {
            int b   = wt - Dc;
            int cid = com_id[b];
            float th = theta[cid];
            float s = 0.f;
            #pragma unroll
            for (int i = 0; i < 8; i++) {
                int d = lane*8 + i;
                float m = (1.f - th) * company_emb[b*Dc + d] + th * comp_table[(size_t)cid*Dc + d];
                s += m * w_fc[d];
            }
            s = warp_sum(s);
            if (lane == 0) g_comp[b] = s + b_fc[0];
        } else if (wt == Dc + Bc) {
            float s = warp_sum(dot8(b_proj + lane*8, w_ff + lane*8));
            if (lane == 0) g_c0 = s;
        }
        __syncthreads();
        if (t == 0) { __threadfence(); atomicAdd(&g_prep_done, 1); }

    } else if (bid == NPREPB - 1) {
        // ======================= bitmap =======================
        // Touched bits from index lists only. Idempotent; never cleared.
        for (int e = t; e < Bc * (KNc + KHc); e += 256) {
            int b = e / (KNc + KHc);
            int i = e % (KNc + KHc);
            int f = (i < KNc) ? now_nodes[b*KNc + i] : his_nodes[b*KHc + (i - KNc)];
            atomicOr(&g_bitmap[b*BMWORDS + (f >> 5)], 1u << (f & 31));
        }
        __syncthreads();
        if (t == 0) { __threadfence(); atomicAdd(&g_prep_done, 1); }

    } else if (bid < NPREPB + NHIS) {
        // ======================= his =======================
        float (*rfe)[Dc] = (float (*)[Dc])smraw;                   // 8192 B
        float (*red)[4]  = (float (*)[4])(smraw + 8192);           // 128 B
        float* w2v_s     = (float*)(smraw + 8320);                 // 512 B
        float* c2_s      = (float*)(smraw + 8832);                 // 4 B
        int j = t & 127, h = t >> 7;
        int slot0 = (bid - NPREPB) * NTH;

        #pragma unroll
        for (int i = t; i < NTH*Dc/4; i += 256) {
            int n  = i >> 6;
            int c4 = i & 63;
            int f  = his_nodes[slot0 + n];
            ((float4*)rfe[n])[c4] = ((const float4*)(raw_field_embed + (size_t)f*Dc))[c4];
        }
        #pragma unroll
        for (int r = 0; r < 16; r++) {
            int jr = warp * 16 + r;
            float s = warp_sum(dot8(W2 + (size_t)jr*Dc + lane*8, w_ff + lane*8));
            if (lane == 0) w2v_s[jr] = s;
        }
        if (warp == 0) {
            float s = warp_sum(dot8(b2 + lane*8, w_ff + lane*8));
            if (lane == 0) *c2_s = s;
        }
        __syncthreads();

        float bj = b1[j];
        float acc0 = bj, acc1 = bj, acc2 = bj, acc3 = bj;
        int nb = h * 4;
        #pragma unroll 4
        for (int k = 0; k < Dc; k += 4) {
            float wa = W1[(size_t)(k+0)*(Dc/2) + j];
            float wb = W1[(size_t)(k+1)*(Dc/2) + j];
            float wc = W1[(size_t)(k+2)*(Dc/2) + j];
            float wd = W1[(size_t)(k+3)*(Dc/2) + j];
            float4 r0 = *(const float4*)&rfe[nb+0][k];
            float4 r1 = *(const float4*)&rfe[nb+1][k];
            float4 r2 = *(const float4*)&rfe[nb+2][k];
            float4 r3 = *(const float4*)&rfe[nb+3][k];
            acc0 += r0.x*wa + r0.y*wb + r0.z*wc + r0.w*wd;
            acc1 += r1.x*wa + r1.y*wb + r1.z*wc + r1.w*wd;
            acc2 += r2.x*wa + r2.y*wb + r2.z*wc + r2.w*wd;
            acc3 += r3.x*wa + r3.y*wb + r3.z*wc + r3.w*wd;
        }

        float wv = w2v_s[j];
        float p0 = ((acc0 >= 0.f) ? acc0 : 0.01f*acc0) * wv;
        float p1 = ((acc1 >= 0.f) ? acc1 : 0.01f*acc1) * wv;
        float p2 = ((acc2 >= 0.f) ? acc2 : 0.01f*acc2) * wv;
        float p3 = ((acc3 >= 0.f) ? acc3 : 0.01f*acc3) * wv;

        p0 = warp_sum(p0); p1 = warp_sum(p1); p2 = warp_sum(p2); p3 = warp_sum(p3);
        if (lane == 0) { red[warp][0]=p0; red[warp][1]=p1; red[warp][2]=p2; red[warp][3]=p3; }
        __syncthreads();
        if (t < NTH) {
            int n = t, hh = n >> 2, nn = n & 3;
            float s = red[hh*4+0][nn] + red[hh*4+1][nn] + red[hh*4+2][nn] + red[hh*4+3][nn];
            g_hisdot[slot0 + n] = s + *c2_s;
        }
        __syncthreads();
        if (t == 0) { __threadfence(); atomicAdd(&g_his_done, 1); }

    } else if (bid < NPREPB + NHIS + NCORR) {
        // ======================= corr =======================
        float* u_s   = (float*)smraw;             // 1024 B
        float* wff_s = (float*)(smraw + 1024);    // 1024 B
        int*   now_s = (int*)(smraw + 2048);      // 256 B
        int*   his_s = (int*)(smraw + 2304);      // 512 B
        int cid = bid - NPREPB - NHIS;     // 0..95
        int b   = cid / ((KNc + KHc)/8);   // 0..3
        int xb  = cid % ((KNc + KHc)/8);   // 0..23

        // index lists + w_ff don't depend on prep — stage them BEFORE the gate
        wff_s[t] = w_ff[t];
        if (t < KNc) now_s[t] = now_nodes[b*KNc + t];
        if (t < KHc) his_s[t] = his_nodes[b*KHc + t];

        if (t == 0) spin_until(&g_prep_done, NPREPB, 128);
        __syncthreads();
        __threadfence();
        u_s[t] = g_u[t];
        __syncthreads();

        float cb = g_comp[b] + b_ff[0];
        float c0 = g_c0;

        int node = xb * 8 + warp;          // 0 .. 191
        int f = (node < KNc) ? now_s[node] : his_s[node - KNc];

        float a1 = dot8(field_table + (size_t)f*Dc + lane*8, u_s   + lane*8);
        float a2 = dot8(field_emb   + (size_t)f*Dc + lane*8, wff_s + lane*8);
        a1 = warp_sum(a1);
        a2 = warp_sum(a2);

        bool inNow = (now_s[lane] == f) || (now_s[lane + 32] == f);
        unsigned mN = __ballot_sync(0xffffffffu, inNow);

        int jmin = INT_MAX;
        #pragma unroll
        for (int r = 0; r < 4; r++) {
            int j = lane + r*32;
            if (his_s[j] == f && j < jmin) jmin = j;
        }
        #pragma unroll
        for (int o = 16; o > 0; o >>= 1) {
            int oth = __shfl_xor_sync(0xffffffffu, jmin, o);
            jmin = min(jmin, oth);
        }

        float alpha = alpha_fields[f];
        float val = (1.f - alpha) * (a1 + c0) + cb;
        if (mN) val += alpha * a2;

        if (lane == 0) {
            if (jmin != INT_MAX) {
                spin_until(&g_his_done, NHIS, 128);
                __threadfence();
                val += alpha * g_hisdot[b*KHc + jmin];
            }
            // store immediately — dense skips touched entries via bitmap.
            out[(size_t)b*Fc + f] = val;
        }

    } else {
        // ======================= dense (5 passes of 32 rows) =======================
        float4* u_s4 = (float4*)smraw;   // 1 KB
        int db = bid - NPREPB - NHIS - NCORR;   // 0..NMAIN-1

        int grp = lane >> 3, sub = lane & 7;
        int blockBase = db * MROWS;

        // ---- pass-0 loads issued BEFORE the prep gate (input-only data) ----
        int r0a = blockBase + warp * 4;
        int fa  = r0a + grp;
        int fca = (fa < Fc) ? fa : (Fc - 1);
        const float4* rowA = (const float4*)(field_table + (size_t)fca * Dc);
        float4 v[8];
        #pragma unroll
        for (int i = 0; i < 8; i++) v[i] = rowA[sub + 8*i];

        // ---- gate on prep (loads already in flight) ----
        if (t == 0) spin_until(&g_prep_done, NPREPB, 128);
        __syncthreads();
        __threadfence();

        if (t < Dc/4) u_s4[t] = ((const float4*)g_u)[t];
        __syncthreads();

        float addb = g_comp[lane & 3] + b_ff[0] + g_c0;

        #pragma unroll
        for (int p = 0; p < 5; p++) {
            int r0 = blockBase + p * 32 + warp * 4;
            if (p > 0) {
                int f  = r0 + grp;
                int fc = (f < Fc) ? f : (Fc - 1);
                const float4* row = (const float4*)(field_table + (size_t)fc * Dc);
                #pragma unroll
                for (int i = 0; i < 8; i++) v[i] = row[sub + 8*i];
            }

            float acc = 0.f;
            #pragma unroll
            for (int i = 0; i < 8; i++) {
                float4 uu = u_s4[sub + 8*i];
                acc += v[i].x*uu.x + v[i].y*uu.y + v[i].z*uu.z + v[i].w*uu.w;
            }
            // reduce within 8-lane group
            acc += __shfl_xor_sync(0xffffffffu, acc, 4);
            acc += __shfl_xor_sync(0xffffffffu, acc, 2);
            acc += __shfl_xor_sync(0xffffffffu, acc, 1);
            // assemble the 4 group sums warp-wide
            float t1 = __shfl_xor_sync(0xffffffffu, acc, 8);
            float t2 = __shfl_xor_sync(0xffffffffu, acc, 16);
            float t3 = __shfl_xor_sync(0xffffffffu, t1, 16);

            if (lane < 8) {
                int b = lane & 3, h = lane >> 2;
                int fr = r0 + 2*h;
                if (fr < Fc) {          // Fc even & fr even -> pair fully in/out
                    unsigned w  = g_bitmap[b*BMWORDS + (fr >> 5)];
                    unsigned m0 = (w >> (fr & 31)) & 1u;
                    unsigned m1 = (w >> ((fr & 31) + 1)) & 1u;
                    float2 q;
                    q.x = (h ? t2 : acc) + addb;
                    q.y = (h ? t3 : t1)  + addb;
                    if (!(m0 | m1)) {
                        *(float2*)(out + (size_t)b*Fc + fr) = q;
                    } else {
                        if (!m0) out[(size_t)b*Fc + fr]     = q.x;
                        if (!m1) out[(size_t)b*Fc + fr + 1] = q.y;
                    }
                }
            }
        }
    }

    // ---- common exit: last block out resets counters for the next replay ----
    __syncthreads();
    if (t == 0) {
        __threadfence();
        int v = atomicAdd(&g_all, 1);
        if (v == GRIDTOT - 1) {      // no block ever waits on g_all -> safe
            g_prep_done = 0;
            g_his_done  = 0;
            g_all       = 0;
        }
    }
}

// ---------------------------------------------------------------------------
extern "C" void kernel_launch(void* const* d_in, const int* in_sizes, int n_in,
                              void* d_out, int out_size)
{
    const float* company_emb     = (const float*)d_in[0];
    const float* field_emb       = (const float*)d_in[1];
    const float* raw_field_embed = (const float*)d_in[2];
    const float* comp_table      = (const float*)d_in[3];
    const float* field_table     = (const float*)d_in[4];
    const float* W_proj          = (const float*)d_in[5];
    const float* b_proj          = (const float*)d_in[6];
    const float* theta           = (const float*)d_in[7];
    const float* alpha_fields    = (const float*)d_in[8];
    const float* w_ff            = (const float*)d_in[9];
    const float* b_ff            = (const float*)d_in[10];
    const float* w_fc            = (const float*)d_in[11];
    const float* b_fc            = (const float*)d_in[12];
    const float* W1              = (const float*)d_in[13];
    const float* b1              = (const float*)d_in[14];
    const float* W2              = (const float*)d_in[15];
    const float* b2              = (const float*)d_in[16];
    const int*   now_nodes       = (const int*)d_in[17];
    const int*   his_nodes       = (const int*)d_in[18];
    const int*   com_id          = (const int*)d_in[19];
    float* out = (float*)d_out;

    mega_kernel<<<GRIDTOT, 256>>>(
        field_table, field_emb, raw_field_embed, alpha_fields, w_ff, b_ff,
        W1, b1, W2, b2, W_proj, b_proj, theta, w_fc, b_fc,
        company_emb, comp_table, com_id, now_nodes, his_nodes, out);
}